// round 16
// baseline (speedup 1.0000x reference)
#include <cuda_runtime.h>
#include <cuda_fp16.h>
#include <cstdint>

#define Ndim 1024
#define Mdim 1024
#define Tdim 64
#define Ddim 128

#define BN 64
#define BM 64
#define BT 4
#define KC 16             // halves per K chunk
#define NKC (Ddim / KC)   // 8
#define PADK 24           // row stride in halves (48B: 16B-aligned, conflict-free)
#define THREADS 256

#define WA_BYTES (64 * PADK * 2)            // 3072  (warp A slice)
#define WB_BYTES (32 * PADK * 2)            // 1536  (warp B half-slice)
#define WARP_STAGE (WA_BYTES + WB_BYTES)    // 4608
#define WARP_BYTES (2 * WARP_STAGE)         // 9216  (2 stages)
#define SMEM_TOTAL (8 * WARP_BYTES)         // 73728 >= epilogue overlay 67584
#define STAGE_T_STRIDE (BN * 66)            // floats per t-plane

__device__ float  g_s1[Ndim * Tdim];
__device__ float  g_s2[Mdim * Tdim];
__device__ __half g_h1[(size_t)Ndim * Tdim * Ddim];
__device__ __half g_h2[(size_t)Mdim * Tdim * Ddim];

// ---------------- helpers ----------------
__device__ __forceinline__ uint32_t smem_u32(const void* p) {
    uint32_t a;
    asm("{ .reg .u64 t; cvta.to.shared.u64 t, %1; cvt.u32.u64 %0, t; }" : "=r"(a) : "l"(p));
    return a;
}
__device__ __forceinline__ void cp_async16(uint32_t dst, const void* src) {
    asm volatile("cp.async.cg.shared.global [%0], [%1], 16;" :: "r"(dst), "l"(src));
}
__device__ __forceinline__ void cp_commit() {
    asm volatile("cp.async.commit_group;" ::: "memory");
}
template <int N>
__device__ __forceinline__ void cp_wait() {
    asm volatile("cp.async.wait_group %0;" :: "n"(N) : "memory");
}

// fp16-accumulator MMA
__device__ __forceinline__ void mma16816h(uint32_t* c, uint32_t a0, uint32_t a1,
                                          uint32_t a2, uint32_t a3,
                                          uint32_t b0, uint32_t b1) {
    asm volatile(
        "mma.sync.aligned.m16n8k16.row.col.f16.f16.f16.f16 "
        "{%0,%1}, {%2,%3,%4,%5}, {%6,%7}, {%0,%1};\n"
        : "+r"(c[0]), "+r"(c[1])
        : "r"(a0), "r"(a1), "r"(a2), "r"(a3), "r"(b0), "r"(b1));
}

// ---------------------------------------------------------------------------
// Kernel 1: fused fp16 convert + squared row norms. One warp per (row, t).
// ---------------------------------------------------------------------------
__global__ void prep_kernel(const float* __restrict__ X1,
                            const float* __restrict__ X2) {
    int gwarp = (blockIdx.x * blockDim.x + threadIdx.x) >> 5;
    int lane  = threadIdx.x & 31;
    const float* src;
    float* ndst;
    __half* hdst;
    int row;
    if (gwarp < Ndim * Tdim) { src = X1; ndst = g_s1; hdst = g_h1; row = gwarp; }
    else                     { src = X2; ndst = g_s2; hdst = g_h2; row = gwarp - Ndim * Tdim; }
    const float4 v = *((const float4*)(src + (size_t)row * Ddim) + lane);
    __half2 h01 = __floats2half2_rn(v.x, v.y);
    __half2 h23 = __floats2half2_rn(v.z, v.w);
    uint2 packed;
    packed.x = *(uint32_t*)&h01;
    packed.y = *(uint32_t*)&h23;
    *(uint2*)(hdst + (size_t)row * Ddim + lane * 4) = packed;
    float s = v.x * v.x + v.y * v.y + v.z * v.z + v.w * v.w;
    #pragma unroll
    for (int o = 16; o > 0; o >>= 1) s += __shfl_down_sync(0xffffffffu, s, o);
    if (lane == 0) ndst[row] = s;
}

// ---------------------------------------------------------------------------
// Kernel 2: batched cross-GEMM via mma.sync, fp16 accumulators.
// DECOUPLED WARP PIPELINES: each warp cp.asyncs its own A + B-half chunk
// into warp-private smem and waits on its own group — ZERO mainloop barriers.
// CTA: 256 threads = 8 warps = 4 t-planes x 2 m-halves, warp tile 64n x 32m.
// 3 CTAs/SM. Grid: t fastest -> 16B writes merge into full sectors.
// ---------------------------------------------------------------------------
__global__ __launch_bounds__(THREADS, 3)
void cross_mma_kernel(float* __restrict__ Y) {
    extern __shared__ char smem[];
    const uint32_t sbase = smem_u32(smem);

    const int tid  = threadIdx.x;
    const int lane = tid & 31;
    const int wid  = tid >> 5;
    const int tp   = wid >> 1;   // t-plane 0..3
    const int mh   = wid & 1;    // m-half 0..1

    const int t0 = blockIdx.x * BT;    // t fastest
    const int m0 = blockIdx.y * BM;
    const int n0 = blockIdx.z * BN;

    const int lr = lane >> 2;          // 0..7
    const int lc = (lane & 3) * 2;     // 0,2,4,6
    const int tt = t0 + tp;

    const uint32_t wbase = sbase + wid * WARP_BYTES;

    // per-thread loader coordinates: lane -> (row-within-16, 16B segment)
    const int rowh = lane >> 1;        // 0..15
    const int seg  = lane & 1;         // 0..1

    uint32_t acc[4][4][2];             // fp16x2 accumulators
    #pragma unroll
    for (int i = 0; i < 4; ++i)
        #pragma unroll
        for (int j = 0; j < 4; ++j) { acc[i][j][0] = 0u; acc[i][j][1] = 0u; }

    // ---- warp-private loader: 6 cp.async per thread per chunk ----
    auto load_chunk = [&](int cc, int st) {
        const uint32_t base = wbase + st * WARP_STAGE;
        #pragma unroll
        for (int j = 0; j < 4; ++j) {              // A: 64 rows
            int r = j * 16 + rowh;
            const __half* g = g_h1 + ((size_t)(n0 + r) * Tdim + tt) * Ddim
                              + cc * KC + seg * 8;
            cp_async16(base + r * (PADK * 2) + seg * 16, g);
        }
        #pragma unroll
        for (int j = 0; j < 2; ++j) {              // B: this warp's 32 m-rows
            int r = j * 16 + rowh;
            const __half* g = g_h2 + ((size_t)(m0 + mh * 32 + r) * Tdim + tt) * Ddim
                              + cc * KC + seg * 8;
            cp_async16(base + WA_BYTES + r * (PADK * 2) + seg * 16, g);
        }
        cp_commit();
    };

    load_chunk(0, 0);
    load_chunk(1, 1);

    for (int cc = 0; cc < NKC; ++cc) {
        if (cc + 2 < NKC) {
            cp_wait<1>();                   // chunk cc landed (own group)
        } else if (cc + 1 < NKC) {
            cp_wait<1>();
        } else {
            cp_wait<0>();
        }
        const uint32_t cbase = wbase + (cc & 1) * WARP_STAGE;
        const __half* Ah = (const __half*)(smem + (cbase - sbase));
        const __half* Bh = (const __half*)(smem + (cbase - sbase) + WA_BYTES);

        uint32_t b0[4], b1[4];
        #pragma unroll
        for (int mi = 0; mi < 4; ++mi) {
            const __half* bp = Bh + (mi * 8 + lr) * PADK + lc;   // local rows
            b0[mi] = *(const uint32_t*)(bp);
            b1[mi] = *(const uint32_t*)(bp + 8);
        }
        #pragma unroll
        for (int ni = 0; ni < 4; ++ni) {
            const __half* ap = Ah + (ni * 16 + lr) * PADK + lc;
            uint32_t a0 = *(const uint32_t*)(ap);
            uint32_t a1 = *(const uint32_t*)(ap + 8 * PADK);
            uint32_t a2 = *(const uint32_t*)(ap + 8);
            uint32_t a3 = *(const uint32_t*)(ap + 8 * PADK + 8);
            #pragma unroll
            for (int mi = 0; mi < 4; ++mi)
                mma16816h(acc[ni][mi], a0, a1, a2, a3, b0[mi], b1[mi]);
        }
        // prefetch chunk cc+2 into the buffer just consumed (same warp only)
        if (cc + 2 < NKC) load_chunk(cc + 2, cc & 1);
    }
    __syncthreads();      // mainloop done everywhere; smem reusable for staging

    // ---- epilogue: convert, combine with norms, stage [t][n][66] ----
    const float invD = 1.0f / (float)Ddim;
    float s1a[4], s1b[4], s2a[4], s2b[4];
    #pragma unroll
    for (int ni = 0; ni < 4; ++ni) {
        s1a[ni] = __ldg(&g_s1[(n0 + ni * 16 + lr) * Tdim + tt]);
        s1b[ni] = __ldg(&g_s1[(n0 + ni * 16 + lr + 8) * Tdim + tt]);
    }
    #pragma unroll
    for (int mi = 0; mi < 4; ++mi) {
        int mg = m0 + mh * 32 + mi * 8 + lc;
        s2a[mi] = __ldg(&g_s2[mg * Tdim + tt]);
        s2b[mi] = __ldg(&g_s2[(mg + 1) * Tdim + tt]);
    }

    float* stage = (float*)smem;
    float* plane = stage + tp * STAGE_T_STRIDE;
    #pragma unroll
    for (int ni = 0; ni < 4; ++ni) {
        #pragma unroll
        for (int mi = 0; mi < 4; ++mi) {
            int r  = ni * 16 + lr;
            int m2 = mh * 32 + mi * 8 + lc;
            float2 lo = __half22float2(*(__half2*)&acc[ni][mi][0]);  // row r
            float2 hi = __half22float2(*(__half2*)&acc[ni][mi][1]);  // row r+8
            float2 v0, v1;
            v0.x = (s1a[ni] + s2a[mi] - 2.0f * lo.x) * invD;
            v0.y = (s1a[ni] + s2b[mi] - 2.0f * lo.y) * invD;
            v1.x = (s1b[ni] + s2a[mi] - 2.0f * hi.x) * invD;
            v1.y = (s1b[ni] + s2b[mi] - 2.0f * hi.y) * invD;
            *(float2*)(plane + r * 66 + m2)       = v0;
            *(float2*)(plane + (r + 8) * 66 + m2) = v1;
        }
    }
    __syncthreads();

    // ---- writeback: full 16B (4 t's) per (n,m) ----
    #pragma unroll
    for (int it = 0; it < 16; ++it) {
        int p = tid + it * THREADS;    // 0..4095
        int n = p >> 6;
        int m = p & 63;
        float4 w;
        w.x = stage[0 * STAGE_T_STRIDE + n * 66 + m];
        w.y = stage[1 * STAGE_T_STRIDE + n * 66 + m];
        w.z = stage[2 * STAGE_T_STRIDE + n * 66 + m];
        w.w = stage[3 * STAGE_T_STRIDE + n * 66 + m];
        size_t off = ((size_t)(n0 + n) * Mdim + (m0 + m)) * Tdim + t0;
        *(float4*)(Y + off) = w;
    }
}

// ---------------------------------------------------------------------------
extern "C" void kernel_launch(void* const* d_in, const int* in_sizes, int n_in,
                              void* d_out, int out_size) {
    const float* X1 = (const float*)d_in[0];
    const float* X2 = (const float*)d_in[1];
    float* Y = (float*)d_out;

    int total_warps = 2 * Ndim * Tdim;
    int blocks = (total_warps * 32) / 256;
    prep_kernel<<<blocks, 256>>>(X1, X2);

    cudaFuncSetAttribute(cross_mma_kernel,
                         cudaFuncAttributeMaxDynamicSharedMemorySize, SMEM_TOTAL);
    dim3 grid(Tdim / BT, Mdim / BM, Ndim / BN);   // 16 x 16 x 16, t fastest
    cross_mma_kernel<<<grid, THREADS, SMEM_TOTAL>>>(Y);
}

// round 17
// speedup vs baseline: 1.1618x; 1.1618x over previous
#include <cuda_runtime.h>
#include <cuda_fp16.h>
#include <cstdint>

#define Ndim 1024
#define Mdim 1024
#define Tdim 64
#define Ddim 128

#define BN 64
#define BM 64
#define BT 4
#define KC 32            // halves per K chunk
#define NKC (Ddim / KC)  // 4
#define PADK 40          // padded smem row stride in halves (80B: conflict-free frags)
#define THREADS 256

#define A_BYTES (BT * BN * PADK * 2)      // 20480
#define B_BYTES (BT * BM * PADK * 2)      // 20480
#define BUF_BYTES (A_BYTES + B_BYTES)     // 40960
#define SMEM_TOTAL (2 * BUF_BYTES)        // 81920 (epilogue stage overlays this)
#define STAGE_T_STRIDE (BN * 66)          // floats per t-plane

__device__ float  g_s1[Ndim * Tdim];
__device__ float  g_s2[Mdim * Tdim];
__device__ __half g_h1[(size_t)Ndim * Tdim * Ddim];
__device__ __half g_h2[(size_t)Mdim * Tdim * Ddim];

// ---------------- helpers ----------------
__device__ __forceinline__ uint32_t smem_u32(const void* p) {
    uint32_t a;
    asm("{ .reg .u64 t; cvta.to.shared.u64 t, %1; cvt.u32.u64 %0, t; }" : "=r"(a) : "l"(p));
    return a;
}
__device__ __forceinline__ void cp_async16(uint32_t dst, const void* src) {
    asm volatile("cp.async.cg.shared.global [%0], [%1], 16;" :: "r"(dst), "l"(src));
}
__device__ __forceinline__ void cp_commit() {
    asm volatile("cp.async.commit_group;" ::: "memory");
}
template <int N>
__device__ __forceinline__ void cp_wait() {
    asm volatile("cp.async.wait_group %0;" :: "n"(N) : "memory");
}

// fp16-accumulator MMA
__device__ __forceinline__ void mma16816h(uint32_t* c, uint32_t a0, uint32_t a1,
                                          uint32_t a2, uint32_t a3,
                                          uint32_t b0, uint32_t b1) {
    asm volatile(
        "mma.sync.aligned.m16n8k16.row.col.f16.f16.f16.f16 "
        "{%0,%1}, {%2,%3,%4,%5}, {%6,%7}, {%0,%1};\n"
        : "+r"(c[0]), "+r"(c[1])
        : "r"(a0), "r"(a1), "r"(a2), "r"(a3), "r"(b0), "r"(b1));
}

// ---------------------------------------------------------------------------
// Kernel 1: fused fp16 convert + squared row norms. One warp per (row, t).
// ---------------------------------------------------------------------------
__global__ void prep_kernel(const float* __restrict__ X1,
                            const float* __restrict__ X2) {
    int gwarp = (blockIdx.x * blockDim.x + threadIdx.x) >> 5;
    int lane  = threadIdx.x & 31;
    const float* src;
    float* ndst;
    __half* hdst;
    int row;
    if (gwarp < Ndim * Tdim) { src = X1; ndst = g_s1; hdst = g_h1; row = gwarp; }
    else                     { src = X2; ndst = g_s2; hdst = g_h2; row = gwarp - Ndim * Tdim; }
    const float4 v = *((const float4*)(src + (size_t)row * Ddim) + lane);
    __half2 h01 = __floats2half2_rn(v.x, v.y);
    __half2 h23 = __floats2half2_rn(v.z, v.w);
    uint2 packed;
    packed.x = *(uint32_t*)&h01;
    packed.y = *(uint32_t*)&h23;
    *(uint2*)(hdst + (size_t)row * Ddim + lane * 4) = packed;
    float s = v.x * v.x + v.y * v.y + v.z * v.z + v.w * v.w;
    #pragma unroll
    for (int o = 16; o > 0; o >>= 1) s += __shfl_down_sync(0xffffffffu, s, o);
    if (lane == 0) ndst[row] = s;
}

// ---------------------------------------------------------------------------
// Kernel 2: batched cross-GEMM via mma.sync, fp16 accumulators.
// R7 champion structure (2 CTAs/SM, 8 warps = 4t x 2mh, warp tile 64n x 32m)
// with register headroom: fp16 acc frees ~40 regs under the 128-reg cap so
// ptxas can batch all 48 fragment LDS of a chunk ahead of the 32 HMMAs.
// Grid: t fastest so 16B writes of adjacent-t CTAs merge into full sectors.
// ---------------------------------------------------------------------------
__global__ __launch_bounds__(THREADS, 2)
void cross_mma_kernel(float* __restrict__ Y) {
    extern __shared__ char smem[];
    const uint32_t sbase = smem_u32(smem);

    const int tid  = threadIdx.x;
    const int lane = tid & 31;
    const int wid  = tid >> 5;
    const int tp   = wid >> 1;   // t-plane 0..3
    const int mh   = wid & 1;    // m-half 0..1

    const int t0 = blockIdx.x * BT;    // t fastest: sector merge across CTAs
    const int m0 = blockIdx.y * BM;
    const int n0 = blockIdx.z * BN;

    const int lr = lane >> 2;          // 0..7
    const int lc = (lane & 3) * 2;     // 0,2,4,6

    uint32_t acc[4][4][2];             // fp16x2 accumulators
    #pragma unroll
    for (int i = 0; i < 4; ++i)
        #pragma unroll
        for (int j = 0; j < 4; ++j) { acc[i][j][0] = 0u; acc[i][j][1] = 0u; }

    // ---- cp.async loader: 2048 float4 per stage / 256 thr = 8 each ----
    auto load_stage = [&](int cc, int buf) {
        const uint32_t abase = sbase + buf * BUF_BYTES;
        const uint32_t bbase = abase + A_BYTES;
        #pragma unroll
        for (int it = 0; it < 8; ++it) {
            int i = tid + it * THREADS;          // 0..2047
            if (i < 1024) {
                int k4 = i & 3, n = (i >> 2) & 63, t = i >> 8;
                const __half* g = g_h1 + ((size_t)(n0 + n) * Tdim + (t0 + t)) * Ddim
                                  + cc * KC + k4 * 8;
                cp_async16(abase + t * (BN * PADK * 2) + n * (PADK * 2) + k4 * 16, g);
            } else {
                int j = i - 1024;
                int k4 = j & 3, m = (j >> 2) & 63, t = j >> 8;
                const __half* g = g_h2 + ((size_t)(m0 + m) * Tdim + (t0 + t)) * Ddim
                                  + cc * KC + k4 * 8;
                cp_async16(bbase + t * (BM * PADK * 2) + m * (PADK * 2) + k4 * 16, g);
            }
        }
        cp_commit();
    };

    load_stage(0, 0);

    for (int cc = 0; cc < NKC; ++cc) {
        if (cc + 1 < NKC) {
            load_stage(cc + 1, (cc + 1) & 1);
            cp_wait<1>();     // oldest group (= chunk cc) complete
        } else {
            cp_wait<0>();
        }
        __syncthreads();      // chunk cc visible to all warps

        const int buf = cc & 1;
        const __half* Ah = (const __half*)(smem + buf * BUF_BYTES) + tp * (BN * PADK);
        const __half* Bh = (const __half*)(smem + buf * BUF_BYTES + A_BYTES) + tp * (BM * PADK);

        // ---- batch ALL fragment loads for both k16 steps (48 LDS) ----
        uint32_t bf[2][4][2];
        uint32_t af[2][4][4];
        #pragma unroll
        for (int s = 0; s < 2; ++s) {
            const int kb = s * 16;
            #pragma unroll
            for (int mi = 0; mi < 4; ++mi) {
                const __half* bp = Bh + (mh * 32 + mi * 8 + lr) * PADK + kb + lc;
                bf[s][mi][0] = *(const uint32_t*)(bp);
                bf[s][mi][1] = *(const uint32_t*)(bp + 8);
            }
            #pragma unroll
            for (int ni = 0; ni < 4; ++ni) {
                const __half* ap = Ah + (ni * 16 + lr) * PADK + kb + lc;
                af[s][ni][0] = *(const uint32_t*)(ap);
                af[s][ni][1] = *(const uint32_t*)(ap + 8 * PADK);
                af[s][ni][2] = *(const uint32_t*)(ap + 8);
                af[s][ni][3] = *(const uint32_t*)(ap + 8 * PADK + 8);
            }
        }
        // ---- 32 HMMAs, all independent per-acc ----
        #pragma unroll
        for (int s = 0; s < 2; ++s)
            #pragma unroll
            for (int ni = 0; ni < 4; ++ni)
                #pragma unroll
                for (int mi = 0; mi < 4; ++mi)
                    mma16816h(acc[ni][mi], af[s][ni][0], af[s][ni][1],
                              af[s][ni][2], af[s][ni][3],
                              bf[s][mi][0], bf[s][mi][1]);

        __syncthreads();      // all warps done with buf before it is overwritten
    }

    // ---- epilogue: convert, combine with norms, stage [t][n][66] ----
    const float invD = 1.0f / (float)Ddim;
    const int tt = t0 + tp;
    float s1a[4], s1b[4], s2a[4], s2b[4];
    #pragma unroll
    for (int ni = 0; ni < 4; ++ni) {
        s1a[ni] = __ldg(&g_s1[(n0 + ni * 16 + lr) * Tdim + tt]);
        s1b[ni] = __ldg(&g_s1[(n0 + ni * 16 + lr + 8) * Tdim + tt]);
    }
    #pragma unroll
    for (int mi = 0; mi < 4; ++mi) {
        int mg = m0 + mh * 32 + mi * 8 + lc;
        s2a[mi] = __ldg(&g_s2[mg * Tdim + tt]);
        s2b[mi] = __ldg(&g_s2[(mg + 1) * Tdim + tt]);
    }

    float* stage = (float*)smem;
    float* plane = stage + tp * STAGE_T_STRIDE;
    #pragma unroll
    for (int ni = 0; ni < 4; ++ni) {
        #pragma unroll
        for (int mi = 0; mi < 4; ++mi) {
            int r  = ni * 16 + lr;
            int m2 = mh * 32 + mi * 8 + lc;
            float2 lo = __half22float2(*(__half2*)&acc[ni][mi][0]);  // row r
            float2 hi = __half22float2(*(__half2*)&acc[ni][mi][1]);  // row r+8
            float2 v0, v1;
            v0.x = (s1a[ni] + s2a[mi] - 2.0f * lo.x) * invD;
            v0.y = (s1a[ni] + s2b[mi] - 2.0f * lo.y) * invD;
            v1.x = (s1b[ni] + s2a[mi] - 2.0f * hi.x) * invD;
            v1.y = (s1b[ni] + s2b[mi] - 2.0f * hi.y) * invD;
            *(float2*)(plane + r * 66 + m2)       = v0;
            *(float2*)(plane + (r + 8) * 66 + m2) = v1;
        }
    }
    __syncthreads();

    // ---- writeback: full 16B (4 t's) per (n,m) ----
    #pragma unroll
    for (int it = 0; it < 16; ++it) {
        int p = tid + it * THREADS;    // 0..4095
        int n = p >> 6;
        int m = p & 63;
        float4 w;
        w.x = stage[0 * STAGE_T_STRIDE + n * 66 + m];
        w.y = stage[1 * STAGE_T_STRIDE + n * 66 + m];
        w.z = stage[2 * STAGE_T_STRIDE + n * 66 + m];
        w.w = stage[3 * STAGE_T_STRIDE + n * 66 + m];
        size_t off = ((size_t)(n0 + n) * Mdim + (m0 + m)) * Tdim + t0;
        *(float4*)(Y + off) = w;
    }
}

// ---------------------------------------------------------------------------
extern "C" void kernel_launch(void* const* d_in, const int* in_sizes, int n_in,
                              void* d_out, int out_size) {
    const float* X1 = (const float*)d_in[0];
    const float* X2 = (const float*)d_in[1];
    float* Y = (float*)d_out;

    int total_warps = 2 * Ndim * Tdim;
    int blocks = (total_warps * 32) / 256;
    prep_kernel<<<blocks, 256>>>(X1, X2);

    cudaFuncSetAttribute(cross_mma_kernel,
                         cudaFuncAttributeMaxDynamicSharedMemorySize, SMEM_TOTAL);
    dim3 grid(Tdim / BT, Mdim / BM, Ndim / BN);   // 16 x 16 x 16, t fastest
    cross_mma_kernel<<<grid, THREADS, SMEM_TOTAL>>>(Y);
}